// round 2
// baseline (speedup 1.0000x reference)
#include <cuda_runtime.h>
#include <math.h>

// Problem constants
#define BB 2
#define SS 2048
#define HH 1024
#define NHEADS 16
#define DH 64
#define MM (BB * SS)   // 4096 rows

// ---------------- scratch (device globals; no allocation allowed) -----------
__device__ float g_q[MM * HH];
__device__ float g_k[MM * HH];
__device__ float g_v[MM * HH];
__device__ float g_ctx[MM * HH];

// ---------------- GEMM: C = (A[M,K] @ W[K,N] + bias[N]) * scale -------------
#define TBM 128
#define TBN 128
#define TBK 16

__global__ __launch_bounds__(256) void gemm_bias_kernel(
    const float* __restrict__ A, const float* __restrict__ W,
    const float* __restrict__ bias, float* __restrict__ C,
    int M, int N, int Kd, float scale)
{
    __shared__ float As[TBK][TBM];
    __shared__ float Bs[TBK][TBN];

    const int tid = threadIdx.x;
    const int ty = tid >> 4;       // 0..15
    const int tx = tid & 15;       // 0..15
    const int bm = blockIdx.y * TBM;
    const int bn = blockIdx.x * TBN;

    float acc[8][8];
#pragma unroll
    for (int i = 0; i < 8; i++)
#pragma unroll
        for (int j = 0; j < 8; j++) acc[i][j] = 0.0f;

    for (int k0 = 0; k0 < Kd; k0 += TBK) {
        // Load A tile (TBM x TBK), store transposed
#pragma unroll
        for (int i = tid; i < (TBM * TBK) / 4; i += 256) {
            int idx = i * 4;
            int r = idx / TBK;
            int c = idx % TBK;
            float4 v = *reinterpret_cast<const float4*>(
                &A[(size_t)(bm + r) * Kd + k0 + c]);
            As[c + 0][r] = v.x;
            As[c + 1][r] = v.y;
            As[c + 2][r] = v.z;
            As[c + 3][r] = v.w;
        }
        // Load B tile (TBK x TBN)
#pragma unroll
        for (int i = tid; i < (TBK * TBN) / 4; i += 256) {
            int idx = i * 4;
            int r = idx / TBN;
            int c = idx % TBN;
            *reinterpret_cast<float4*>(&Bs[r][c]) =
                *reinterpret_cast<const float4*>(
                    &W[(size_t)(k0 + r) * N + bn + c]);
        }
        __syncthreads();

#pragma unroll
        for (int kk = 0; kk < TBK; kk++) {
            float af[8], bf[8];
#pragma unroll
            for (int i = 0; i < 8; i++) af[i] = As[kk][ty * 8 + i];
#pragma unroll
            for (int j = 0; j < 8; j++) bf[j] = Bs[kk][tx * 8 + j];
#pragma unroll
            for (int i = 0; i < 8; i++)
#pragma unroll
                for (int j = 0; j < 8; j++) acc[i][j] += af[i] * bf[j];
        }
        __syncthreads();
    }

#pragma unroll
    for (int i = 0; i < 8; i++) {
        int r = bm + ty * 8 + i;
#pragma unroll
        for (int j = 0; j < 8; j++) {
            int c = bn + tx * 8 + j;
            C[(size_t)r * N + c] = (acc[i][j] + bias[c]) * scale;
        }
    }
}

// ---------------- Flash attention -------------------------------------------
// grid: (S/64, NHEADS, B), block: 256 threads (16x16), each thread owns a
// 4(q) x 4(k or d) register tile. Online softmax, P staged through Ks buffer.
#define BQ 64
#define BKT 64
#define KSTR 65   // Ks stride (avoids 16-way conflicts on k-major reads)
// smem: Qs 64*64 + Ks 64*65 + Vs 64*64
#define SMEM_FLASH ((64 * 64 + 64 * KSTR + 64 * 64) * 4)

__global__ __launch_bounds__(256) void flash_kernel(
    const float* __restrict__ Q, const float* __restrict__ K,
    const float* __restrict__ V, const float* __restrict__ mask,
    float* __restrict__ Ctx)
{
    extern __shared__ float sm[];
    float* Qs = sm;                       // [64][64]
    float* Ks = sm + 64 * 64;             // [64][KSTR]  (later reused for P)
    float* Vs = Ks + 64 * KSTR;           // [64][64]

    const int tid = threadIdx.x;
    const int ty = tid >> 4;              // 0..15 -> q rows ty*4..+3
    const int tx = tid & 15;              // 0..15 -> k/d cols tx*4..+3
    const int qb = blockIdx.x * BQ;
    const int h = blockIdx.y;
    const int b = blockIdx.z;

    const size_t rowbase = (size_t)b * SS * HH;
    const int hoff = h * DH;
    const float* maskb = mask + (size_t)b * SS * SS;

    // Load Q tile (already scaled by 1/sqrt(dh) in the projection)
    for (int i = tid; i < (BQ * DH) / 4; i += 256) {
        int idx = i * 4;
        int r = idx / DH;
        int c = idx % DH;
        float4 v = *reinterpret_cast<const float4*>(
            &Q[rowbase + (size_t)(qb + r) * HH + hoff + c]);
        *reinterpret_cast<float4*>(&Qs[r * 64 + c]) = v;
    }

    float m_i[4], l_i[4], acc[4][4];
#pragma unroll
    for (int i = 0; i < 4; i++) {
        m_i[i] = -1e30f;
        l_i[i] = 0.0f;
#pragma unroll
        for (int j = 0; j < 4; j++) acc[i][j] = 0.0f;
    }

    for (int t = 0; t < SS / BKT; t++) {
        const int k0 = t * BKT;
        __syncthreads();  // previous PV readers done before overwrite
        // Load K,V tiles
        for (int i = tid; i < (BKT * DH) / 4; i += 256) {
            int idx = i * 4;
            int r = idx / DH;
            int c = idx % DH;
            float4 kv = *reinterpret_cast<const float4*>(
                &K[rowbase + (size_t)(k0 + r) * HH + hoff + c]);
            Ks[r * KSTR + c + 0] = kv.x;
            Ks[r * KSTR + c + 1] = kv.y;
            Ks[r * KSTR + c + 2] = kv.z;
            Ks[r * KSTR + c + 3] = kv.w;
            float4 vv = *reinterpret_cast<const float4*>(
                &V[rowbase + (size_t)(k0 + r) * HH + hoff + c]);
            *reinterpret_cast<float4*>(&Vs[r * 64 + c]) = vv;
        }
        __syncthreads();

        // S = Q K^T for this thread's 4x4 patch
        float s[4][4];
#pragma unroll
        for (int i = 0; i < 4; i++)
#pragma unroll
            for (int j = 0; j < 4; j++) s[i][j] = 0.0f;

#pragma unroll 4
        for (int d = 0; d < DH; d++) {
            float qv[4], kv[4];
#pragma unroll
            for (int i = 0; i < 4; i++) qv[i] = Qs[(ty * 4 + i) * 64 + d];
#pragma unroll
            for (int j = 0; j < 4; j++) kv[j] = Ks[(tx * 4 + j) * KSTR + d];
#pragma unroll
            for (int i = 0; i < 4; i++)
#pragma unroll
                for (int j = 0; j < 4; j++) s[i][j] += qv[i] * kv[j];
        }

        // additive mask
#pragma unroll
        for (int i = 0; i < 4; i++) {
            const float* mrow = maskb + (size_t)(qb + ty * 4 + i) * SS + k0 + tx * 4;
#pragma unroll
            for (int j = 0; j < 4; j++) s[i][j] += mrow[j];
        }

        // online softmax (row reductions across 16 tx lanes via shfl butterfly;
        // each warp holds two ty groups in its 16-lane halves)
#pragma unroll
        for (int i = 0; i < 4; i++) {
            float tm = fmaxf(fmaxf(s[i][0], s[i][1]), fmaxf(s[i][2], s[i][3]));
#pragma unroll
            for (int o = 8; o >= 1; o >>= 1)
                tm = fmaxf(tm, __shfl_xor_sync(0xffffffffu, tm, o));
            float mnew = fmaxf(m_i[i], tm);
            float sum = 0.0f;
#pragma unroll
            for (int j = 0; j < 4; j++) {
                s[i][j] = __expf(s[i][j] - mnew);
                sum += s[i][j];
            }
#pragma unroll
            for (int o = 8; o >= 1; o >>= 1)
                sum += __shfl_xor_sync(0xffffffffu, sum, o);
            float sc = __expf(m_i[i] - mnew);
            l_i[i] = l_i[i] * sc + sum;
            m_i[i] = mnew;
#pragma unroll
            for (int j = 0; j < 4; j++) acc[i][j] *= sc;
        }

        __syncthreads();  // everyone done reading Ks
        // stage P into Ks buffer
#pragma unroll
        for (int i = 0; i < 4; i++)
#pragma unroll
            for (int j = 0; j < 4; j++)
                Ks[(ty * 4 + i) * KSTR + tx * 4 + j] = s[i][j];
        __syncthreads();

        // acc += P @ V   (thread owns q rows ty*4..+3, d cols tx*4..+3)
#pragma unroll 4
        for (int k = 0; k < BKT; k++) {
            float pv[4], vv[4];
#pragma unroll
            for (int i = 0; i < 4; i++) pv[i] = Ks[(ty * 4 + i) * KSTR + k];
#pragma unroll
            for (int j = 0; j < 4; j++) vv[j] = Vs[k * 64 + tx * 4 + j];
#pragma unroll
            for (int i = 0; i < 4; i++)
#pragma unroll
                for (int j = 0; j < 4; j++) acc[i][j] += pv[i] * vv[j];
        }
    }

    // epilogue: normalize and write ctx in [B, S, heads*dh] layout
#pragma unroll
    for (int i = 0; i < 4; i++) {
        float inv = 1.0f / l_i[i];
#pragma unroll
        for (int j = 0; j < 4; j++) {
            Ctx[rowbase + (size_t)(qb + ty * 4 + i) * HH + hoff + tx * 4 + j] =
                acc[i][j] * inv;
        }
    }
}

// ---------------- launch -----------------------------------------------------
extern "C" void kernel_launch(void* const* d_in, const int* in_sizes, int n_in,
                              void* d_out, int out_size)
{
    const float* key   = (const float*)d_in[0];
    const float* value = (const float*)d_in[1];
    const float* query = (const float*)d_in[2];
    const float* mask  = (const float*)d_in[3];
    const float* Wq    = (const float*)d_in[4];
    const float* bq    = (const float*)d_in[5];
    const float* Wk    = (const float*)d_in[6];
    const float* bk    = (const float*)d_in[7];
    const float* Wv    = (const float*)d_in[8];
    const float* bv    = (const float*)d_in[9];
    const float* Wo    = (const float*)d_in[10];
    const float* bo    = (const float*)d_in[11];
    float* out = (float*)d_out;

    float *gq, *gk, *gv, *gctx;
    cudaGetSymbolAddress((void**)&gq, g_q);
    cudaGetSymbolAddress((void**)&gk, g_k);
    cudaGetSymbolAddress((void**)&gv, g_v);
    cudaGetSymbolAddress((void**)&gctx, g_ctx);
    cudaFuncSetAttribute(flash_kernel,
                         cudaFuncAttributeMaxDynamicSharedMemorySize,
                         SMEM_FLASH);

    dim3 ggrid(HH / TBN, MM / TBM);   // (8, 32)

    // projections (Q gets the 1/sqrt(dh) scale folded in, matching reference
    // which scales after bias add)
    gemm_bias_kernel<<<ggrid, 256>>>(query, Wq, bq, gq, MM, HH, HH, 0.125f);
    gemm_bias_kernel<<<ggrid, 256>>>(key,   Wk, bk, gk, MM, HH, HH, 1.0f);
    gemm_bias_kernel<<<ggrid, 256>>>(value, Wv, bv, gv, MM, HH, HH, 1.0f);

    dim3 fgrid(SS / BQ, NHEADS, BB);  // (32, 16, 2)
    flash_kernel<<<fgrid, 256, SMEM_FLASH>>>(gq, gk, gv, mask, gctx);

    gemm_bias_kernel<<<ggrid, 256>>>(gctx, Wo, bo, out, MM, HH, HH, 1.0f);
}

// round 3
// speedup vs baseline: 2.4967x; 2.4967x over previous
#include <cuda_runtime.h>
#include <math.h>

// Problem constants
#define BB 2
#define SS 2048
#define HH 1024
#define NHEADS 16
#define DH 64
#define MM (BB * SS)   // 4096 rows

// ---------------- scratch (device globals; no allocation allowed) -----------
__device__ float g_q[MM * HH];
__device__ float g_k[MM * HH];
__device__ float g_v[MM * HH];
__device__ float g_ctx[MM * HH];

// ---------------- tf32 helpers ----------------------------------------------
__device__ __forceinline__ unsigned f2tf(float x) {
    unsigned u;
    asm("cvt.rna.tf32.f32 %0, %1;" : "=r"(u) : "f"(x));
    return u;
}

__device__ __forceinline__ void mma_tf32(float c[4],
                                         unsigned a0, unsigned a1,
                                         unsigned a2, unsigned a3,
                                         unsigned b0, unsigned b1) {
    asm volatile(
        "mma.sync.aligned.m16n8k8.row.col.f32.tf32.tf32.f32 "
        "{%0,%1,%2,%3}, {%4,%5,%6,%7}, {%8,%9}, {%0,%1,%2,%3};"
        : "+f"(c[0]), "+f"(c[1]), "+f"(c[2]), "+f"(c[3])
        : "r"(a0), "r"(a1), "r"(a2), "r"(a3), "r"(b0), "r"(b1));
}

// ---------------- GEMM: C = (A[M,K] @ W[K,N] + bias) * scale ----------------
// 128x128 block tile, BK=16, 8 warps in 2(M) x 4(N), warp tile 64x32.
#define GBM 128
#define GBN 128
#define GBK 16
#define GSTR 136   // 136 % 32 == 8 -> conflict-free frag loads (k span 4, mn span 8)

__global__ __launch_bounds__(256) void gemm_tf32(
    const float* __restrict__ A, const float* __restrict__ W,
    const float* __restrict__ bias, float* __restrict__ C,
    int M, int N, int Kd, float scale)
{
    __shared__ unsigned As[2][GBK * GSTR];  // [k][m] (transposed)
    __shared__ unsigned Bs[2][GBK * GSTR];  // [k][n]

    const int tid = threadIdx.x;
    const int lane = tid & 31;
    const int wid = tid >> 5;
    const int wm = (wid & 1) * 64;   // warp M offset within block
    const int wn = (wid >> 1) * 32;  // warp N offset within block
    const int r4 = lane >> 2;        // 0..7
    const int c4 = lane & 3;         // 0..3
    const int bm = blockIdx.y * GBM;
    const int bn = blockIdx.x * GBN;

    // A staging: thread handles rows am0, am0+64 with k-chunk ak..ak+3
    const int am0 = tid >> 2;         // 0..63
    const int ak  = (tid & 3) * 4;    // 0,4,8,12
    // B staging: thread handles k rows bk0, bk0+8 with n-chunk bn4..+3
    const int bk0 = tid >> 5;         // 0..7
    const int bn4 = (tid & 31) * 4;   // 0..124

    float acc[16][4];
#pragma unroll
    for (int i = 0; i < 16; i++)
#pragma unroll
        for (int j = 0; j < 4; j++) acc[i][j] = 0.0f;

    float4 ra0, ra1, rb0, rb1;
    const int nk = Kd / GBK;

    // prologue: load tile 0
    ra0 = *(const float4*)&A[(size_t)(bm + am0) * Kd + ak];
    ra1 = *(const float4*)&A[(size_t)(bm + am0 + 64) * Kd + ak];
    rb0 = *(const float4*)&W[(size_t)(bk0) * N + bn + bn4];
    rb1 = *(const float4*)&W[(size_t)(bk0 + 8) * N + bn + bn4];
    {
        As[0][(ak + 0) * GSTR + am0] = f2tf(ra0.x);
        As[0][(ak + 1) * GSTR + am0] = f2tf(ra0.y);
        As[0][(ak + 2) * GSTR + am0] = f2tf(ra0.z);
        As[0][(ak + 3) * GSTR + am0] = f2tf(ra0.w);
        As[0][(ak + 0) * GSTR + am0 + 64] = f2tf(ra1.x);
        As[0][(ak + 1) * GSTR + am0 + 64] = f2tf(ra1.y);
        As[0][(ak + 2) * GSTR + am0 + 64] = f2tf(ra1.z);
        As[0][(ak + 3) * GSTR + am0 + 64] = f2tf(ra1.w);
        uint4 u0 = make_uint4(f2tf(rb0.x), f2tf(rb0.y), f2tf(rb0.z), f2tf(rb0.w));
        uint4 u1 = make_uint4(f2tf(rb1.x), f2tf(rb1.y), f2tf(rb1.z), f2tf(rb1.w));
        *(uint4*)&Bs[0][bk0 * GSTR + bn4] = u0;
        *(uint4*)&Bs[0][(bk0 + 8) * GSTR + bn4] = u1;
    }
    __syncthreads();

    for (int kt = 0; kt < nk; kt++) {
        const int buf = kt & 1;
        if (kt + 1 < nk) {
            const int k0 = (kt + 1) * GBK;
            ra0 = *(const float4*)&A[(size_t)(bm + am0) * Kd + k0 + ak];
            ra1 = *(const float4*)&A[(size_t)(bm + am0 + 64) * Kd + k0 + ak];
            rb0 = *(const float4*)&W[(size_t)(k0 + bk0) * N + bn + bn4];
            rb1 = *(const float4*)&W[(size_t)(k0 + bk0 + 8) * N + bn + bn4];
        }

#pragma unroll
        for (int ks = 0; ks < 2; ks++) {
            const int kb = ks * 8;
            unsigned bf[4][2];
#pragma unroll
            for (int nt = 0; nt < 4; nt++) {
                const int n = wn + nt * 8 + r4;
                bf[nt][0] = Bs[buf][(kb + c4) * GSTR + n];
                bf[nt][1] = Bs[buf][(kb + c4 + 4) * GSTR + n];
            }
#pragma unroll
            for (int mt = 0; mt < 4; mt++) {
                const int m = wm + mt * 16 + r4;
                unsigned a0 = As[buf][(kb + c4) * GSTR + m];
                unsigned a1 = As[buf][(kb + c4) * GSTR + m + 8];
                unsigned a2 = As[buf][(kb + c4 + 4) * GSTR + m];
                unsigned a3 = As[buf][(kb + c4 + 4) * GSTR + m + 8];
#pragma unroll
                for (int nt = 0; nt < 4; nt++)
                    mma_tf32(acc[mt * 4 + nt], a0, a1, a2, a3, bf[nt][0], bf[nt][1]);
            }
        }
        __syncthreads();

        if (kt + 1 < nk) {
            const int nb = (kt + 1) & 1;
            As[nb][(ak + 0) * GSTR + am0] = f2tf(ra0.x);
            As[nb][(ak + 1) * GSTR + am0] = f2tf(ra0.y);
            As[nb][(ak + 2) * GSTR + am0] = f2tf(ra0.z);
            As[nb][(ak + 3) * GSTR + am0] = f2tf(ra0.w);
            As[nb][(ak + 0) * GSTR + am0 + 64] = f2tf(ra1.x);
            As[nb][(ak + 1) * GSTR + am0 + 64] = f2tf(ra1.y);
            As[nb][(ak + 2) * GSTR + am0 + 64] = f2tf(ra1.z);
            As[nb][(ak + 3) * GSTR + am0 + 64] = f2tf(ra1.w);
            uint4 u0 = make_uint4(f2tf(rb0.x), f2tf(rb0.y), f2tf(rb0.z), f2tf(rb0.w));
            uint4 u1 = make_uint4(f2tf(rb1.x), f2tf(rb1.y), f2tf(rb1.z), f2tf(rb1.w));
            *(uint4*)&Bs[nb][bk0 * GSTR + bn4] = u0;
            *(uint4*)&Bs[nb][(bk0 + 8) * GSTR + bn4] = u1;
            __syncthreads();
        }
    }

    // epilogue
#pragma unroll
    for (int mt = 0; mt < 4; mt++) {
#pragma unroll
        for (int nt = 0; nt < 4; nt++) {
            const int row0 = bm + wm + mt * 16 + r4;
            const int col = bn + wn + nt * 8 + 2 * c4;
            float* c0 = &C[(size_t)row0 * N + col];
            float* c1 = &C[(size_t)(row0 + 8) * N + col];
            const float b0 = bias[col], b1 = bias[col + 1];
            c0[0] = (acc[mt * 4 + nt][0] + b0) * scale;
            c0[1] = (acc[mt * 4 + nt][1] + b1) * scale;
            c1[0] = (acc[mt * 4 + nt][2] + b0) * scale;
            c1[1] = (acc[mt * 4 + nt][3] + b1) * scale;
        }
    }
}

// ---------------- Flash attention (tf32 mma) ---------------------------------
// grid (S/64, NHEADS, B), 128 threads (4 warps). Each warp owns 16 q rows.
// Qs/Ks/Ps use stride 68 (==4 mod 32): conflict-free for row-span-8/col-span-4
// fragment loads. Vs uses stride 72 (==8 mod 32): row-span-4/col-span-8.
#define QSTR 68
#define VSTR 72
#define SMEM_FLASH ((64 * QSTR + 64 * QSTR + 64 * VSTR) * 4)

__global__ __launch_bounds__(128) void flash_tf32(
    const float* __restrict__ Q, const float* __restrict__ K,
    const float* __restrict__ V, const float* __restrict__ mask,
    float* __restrict__ Ctx)
{
    extern __shared__ unsigned smu[];
    unsigned* Qs = smu;                    // [64][QSTR] tf32
    unsigned* Ks = smu + 64 * QSTR;        // [64][QSTR] tf32, reused for P
    unsigned* Vs = Ks + 64 * QSTR;         // [64][VSTR] tf32

    const int tid = threadIdx.x;
    const int lane = tid & 31;
    const int w = tid >> 5;                // warp 0..3
    const int r4 = lane >> 2;              // 0..7
    const int c4 = lane & 3;               // 0..3
    const int qb = blockIdx.x * 64;
    const int h = blockIdx.y;
    const int b = blockIdx.z;

    const size_t base = (size_t)b * SS * HH;
    const int hoff = h * DH;
    const float* maskb = mask + (size_t)b * SS * SS;
    const int qrow = 16 * w + r4;          // this thread's first q row (block-rel)

    // Load Q tile (64x64), convert to tf32
    for (int i = tid; i < 1024; i += 128) {
        const int r = i >> 4, c = (i & 15) * 4;
        float4 v = *(const float4*)&Q[base + (size_t)(qb + r) * HH + hoff + c];
        unsigned* p = &Qs[r * QSTR + c];
        p[0] = f2tf(v.x); p[1] = f2tf(v.y); p[2] = f2tf(v.z); p[3] = f2tf(v.w);
    }

    float oc[8][4];
#pragma unroll
    for (int nt = 0; nt < 8; nt++)
#pragma unroll
        for (int j = 0; j < 4; j++) oc[nt][j] = 0.0f;
    float m0 = -1e30f, m1 = -1e30f, l0 = 0.0f, l1 = 0.0f;

    for (int t = 0; t < SS / 64; t++) {
        const int k0 = t * 64;
        __syncthreads();  // prev iter done with Ks(P)/Vs
        for (int i = tid; i < 1024; i += 128) {
            const int r = i >> 4, c = (i & 15) * 4;
            float4 kv = *(const float4*)&K[base + (size_t)(k0 + r) * HH + hoff + c];
            unsigned* pk = &Ks[r * QSTR + c];
            pk[0] = f2tf(kv.x); pk[1] = f2tf(kv.y); pk[2] = f2tf(kv.z); pk[3] = f2tf(kv.w);
            float4 vv = *(const float4*)&V[base + (size_t)(k0 + r) * HH + hoff + c];
            unsigned* pv = &Vs[r * VSTR + c];
            pv[0] = f2tf(vv.x); pv[1] = f2tf(vv.y); pv[2] = f2tf(vv.z); pv[3] = f2tf(vv.w);
        }
        __syncthreads();

        // S = Q @ K^T  (warp strip 16 x 64)
        float sc[8][4];
#pragma unroll
        for (int nt = 0; nt < 8; nt++)
#pragma unroll
            for (int j = 0; j < 4; j++) sc[nt][j] = 0.0f;

#pragma unroll
        for (int ks = 0; ks < 8; ks++) {
            const int kb = ks * 8;
            unsigned a0 = Qs[(16 * w + r4) * QSTR + kb + c4];
            unsigned a1 = Qs[(16 * w + r4 + 8) * QSTR + kb + c4];
            unsigned a2 = Qs[(16 * w + r4) * QSTR + kb + c4 + 4];
            unsigned a3 = Qs[(16 * w + r4 + 8) * QSTR + kb + c4 + 4];
#pragma unroll
            for (int nt = 0; nt < 8; nt++) {
                unsigned b0 = Ks[(nt * 8 + r4) * QSTR + kb + c4];
                unsigned b1 = Ks[(nt * 8 + r4) * QSTR + kb + c4 + 4];
                mma_tf32(sc[nt], a0, a1, a2, a3, b0, b1);
            }
        }

        // additive mask
#pragma unroll
        for (int nt = 0; nt < 8; nt++) {
            const float* mr0 = maskb + (size_t)(qb + qrow) * SS + k0 + nt * 8 + 2 * c4;
            sc[nt][0] += mr0[0];
            sc[nt][1] += mr0[1];
            const float* mr1 = mr0 + (size_t)8 * SS;
            sc[nt][2] += mr1[0];
            sc[nt][3] += mr1[1];
        }

        // online softmax (rows qrow and qrow+8)
        float tm0 = -1e30f, tm1 = -1e30f;
#pragma unroll
        for (int nt = 0; nt < 8; nt++) {
            tm0 = fmaxf(tm0, fmaxf(sc[nt][0], sc[nt][1]));
            tm1 = fmaxf(tm1, fmaxf(sc[nt][2], sc[nt][3]));
        }
#pragma unroll
        for (int o = 1; o <= 2; o <<= 1) {
            tm0 = fmaxf(tm0, __shfl_xor_sync(0xffffffffu, tm0, o));
            tm1 = fmaxf(tm1, __shfl_xor_sync(0xffffffffu, tm1, o));
        }
        const float nm0 = fmaxf(m0, tm0), nm1 = fmaxf(m1, tm1);
        float sum0 = 0.0f, sum1 = 0.0f;
#pragma unroll
        for (int nt = 0; nt < 8; nt++) {
            sc[nt][0] = __expf(sc[nt][0] - nm0);
            sc[nt][1] = __expf(sc[nt][1] - nm0);
            sc[nt][2] = __expf(sc[nt][2] - nm1);
            sc[nt][3] = __expf(sc[nt][3] - nm1);
            sum0 += sc[nt][0] + sc[nt][1];
            sum1 += sc[nt][2] + sc[nt][3];
        }
#pragma unroll
        for (int o = 1; o <= 2; o <<= 1) {
            sum0 += __shfl_xor_sync(0xffffffffu, sum0, o);
            sum1 += __shfl_xor_sync(0xffffffffu, sum1, o);
        }
        const float es0 = __expf(m0 - nm0), es1 = __expf(m1 - nm1);
        l0 = l0 * es0 + sum0; m0 = nm0;
        l1 = l1 * es1 + sum1; m1 = nm1;
#pragma unroll
        for (int nt = 0; nt < 8; nt++) {
            oc[nt][0] *= es0; oc[nt][1] *= es0;
            oc[nt][2] *= es1; oc[nt][3] *= es1;
        }

        __syncthreads();  // all warps done reading Ks as B-frags
        // stage P (tf32) into own 16-row strip of Ks buffer
#pragma unroll
        for (int nt = 0; nt < 8; nt++) {
            uint2 p0 = make_uint2(f2tf(sc[nt][0]), f2tf(sc[nt][1]));
            uint2 p1 = make_uint2(f2tf(sc[nt][2]), f2tf(sc[nt][3]));
            *(uint2*)&Ks[(16 * w + r4) * QSTR + nt * 8 + 2 * c4] = p0;
            *(uint2*)&Ks[(16 * w + r4 + 8) * QSTR + nt * 8 + 2 * c4] = p1;
        }
        __syncwarp();

        // O += P @ V
#pragma unroll
        for (int ks = 0; ks < 8; ks++) {
            const int kb = ks * 8;
            unsigned a0 = Ks[(16 * w + r4) * QSTR + kb + c4];
            unsigned a1 = Ks[(16 * w + r4 + 8) * QSTR + kb + c4];
            unsigned a2 = Ks[(16 * w + r4) * QSTR + kb + c4 + 4];
            unsigned a3 = Ks[(16 * w + r4 + 8) * QSTR + kb + c4 + 4];
#pragma unroll
            for (int nt = 0; nt < 8; nt++) {
                unsigned b0 = Vs[(kb + c4) * VSTR + nt * 8 + r4];
                unsigned b1 = Vs[(kb + c4 + 4) * VSTR + nt * 8 + r4];
                mma_tf32(oc[nt], a0, a1, a2, a3, b0, b1);
            }
        }
    }

    // epilogue: normalize, write ctx in [B,S,heads*dh]
    const float il0 = 1.0f / l0, il1 = 1.0f / l1;
#pragma unroll
    for (int nt = 0; nt < 8; nt++) {
        const int col = hoff + nt * 8 + 2 * c4;
        float* o0 = &Ctx[base + (size_t)(qb + qrow) * HH + col];
        float* o1 = &Ctx[base + (size_t)(qb + qrow + 8) * HH + col];
        o0[0] = oc[nt][0] * il0;
        o0[1] = oc[nt][1] * il0;
        o1[0] = oc[nt][2] * il1;
        o1[1] = oc[nt][3] * il1;
    }
}

// ---------------- launch -----------------------------------------------------
extern "C" void kernel_launch(void* const* d_in, const int* in_sizes, int n_in,
                              void* d_out, int out_size)
{
    const float* key   = (const float*)d_in[0];
    const float* value = (const float*)d_in[1];
    const float* query = (const float*)d_in[2];
    const float* mask  = (const float*)d_in[3];
    const float* Wq    = (const float*)d_in[4];
    const float* bq    = (const float*)d_in[5];
    const float* Wk    = (const float*)d_in[6];
    const float* bk    = (const float*)d_in[7];
    const float* Wv    = (const float*)d_in[8];
    const float* bv    = (const float*)d_in[9];
    const float* Wo    = (const float*)d_in[10];
    const float* bo    = (const float*)d_in[11];
    float* out = (float*)d_out;

    float *gq, *gk, *gv, *gctx;
    cudaGetSymbolAddress((void**)&gq, g_q);
    cudaGetSymbolAddress((void**)&gk, g_k);
    cudaGetSymbolAddress((void**)&gv, g_v);
    cudaGetSymbolAddress((void**)&gctx, g_ctx);
    cudaFuncSetAttribute(flash_tf32,
                         cudaFuncAttributeMaxDynamicSharedMemorySize,
                         SMEM_FLASH);

    dim3 ggrid(HH / GBN, MM / GBM);   // (8, 32)

    // projections (Q gets 1/sqrt(dh) folded in; reference scales after bias)
    gemm_tf32<<<ggrid, 256>>>(query, Wq, bq, gq, MM, HH, HH, 0.125f);
    gemm_tf32<<<ggrid, 256>>>(key,   Wk, bk, gk, MM, HH, HH, 1.0f);
    gemm_tf32<<<ggrid, 256>>>(value, Wv, bv, gv, MM, HH, HH, 1.0f);

    dim3 fgrid(SS / 64, NHEADS, BB);  // (32, 16, 2)
    flash_tf32<<<fgrid, 128, SMEM_FLASH>>>(gq, gk, gv, mask, gctx);

    gemm_tf32<<<ggrid, 256>>>(gctx, Wo, bo, out, MM, HH, HH, 1.0f);
}

// round 5
// speedup vs baseline: 2.5917x; 1.0380x over previous
#include <cuda_runtime.h>
#include <math.h>

// Problem constants
#define BB 2
#define SS 2048
#define HH 1024
#define NHEADS 16
#define DH 64
#define MM (BB * SS)   // 4096 rows

// ---------------- scratch (device globals; no allocation allowed) -----------
__device__ float g_q[MM * HH];
__device__ float g_k[MM * HH];
__device__ float g_v[MM * HH];
__device__ float g_ctx[MM * HH];

// ---------------- helpers ----------------------------------------------------
__device__ __forceinline__ unsigned f2tf(float x) {
    unsigned u;
    asm("cvt.rna.tf32.f32 %0, %1;" : "=r"(u) : "f"(x));
    return u;
}
// round raw fp32 bits (from smem) to tf32
__device__ __forceinline__ unsigned b2tf(unsigned bits) {
    unsigned u;
    asm("cvt.rna.tf32.f32 %0, %1;" : "=r"(u) : "f"(__uint_as_float(bits)));
    return u;
}

__device__ __forceinline__ void mma_tf32(float c[4],
                                         unsigned a0, unsigned a1,
                                         unsigned a2, unsigned a3,
                                         unsigned b0, unsigned b1) {
    asm volatile(
        "mma.sync.aligned.m16n8k8.row.col.f32.tf32.tf32.f32 "
        "{%0,%1,%2,%3}, {%4,%5,%6,%7}, {%8,%9}, {%0,%1,%2,%3};"
        : "+f"(c[0]), "+f"(c[1]), "+f"(c[2]), "+f"(c[3])
        : "r"(a0), "r"(a1), "r"(a2), "r"(a3), "r"(b0), "r"(b1));
}

__device__ __forceinline__ void cpa16(unsigned sdst, const void* gsrc) {
    asm volatile("cp.async.cg.shared.global [%0], [%1], 16;"
                 :: "r"(sdst), "l"(gsrc));
}
__device__ __forceinline__ void cpa_commit() {
    asm volatile("cp.async.commit_group;");
}
__device__ __forceinline__ void cpa_wait1() {
    asm volatile("cp.async.wait_group 1;");
}

// ---------------- GEMM: C = (A[M,K] @ W[K,N] + bias) * scale ----------------
// 128x128 block tile, BK=16, 8 warps (2Mx4N), warp tile 64x32.
// A staged [m][k] stride 36; B staged [k][n] stride 136. cp.async dbl buffer.
// Fragments rounded to tf32 (cvt.rna) at load time.
#define GBM 128
#define GBN 128
#define GBK 16
#define ASTR 36
#define BSTR 136
#define GEMM_SMEM ((2 * GBM * ASTR + 2 * GBK * BSTR) * 4)

__global__ __launch_bounds__(256) void gemm_tf32(
    const float* __restrict__ A, const float* __restrict__ W,
    const float* __restrict__ bias, float* __restrict__ C,
    int M, int N, int Kd, float scale)
{
    extern __shared__ unsigned gsm[];
    unsigned* As = gsm;                       // [2][128][ASTR] raw fp32 bits
    unsigned* Bs = gsm + 2 * GBM * ASTR;      // [2][16][BSTR]
    const unsigned sb = (unsigned)__cvta_generic_to_shared(gsm);
    const unsigned sbB = sb + 2 * GBM * ASTR * 4;

    const int tid = threadIdx.x;
    const int lane = tid & 31;
    const int wid = tid >> 5;
    const int wm = (wid & 1) * 64;
    const int wn = (wid >> 1) * 32;
    const int r4 = lane >> 2;
    const int c4 = lane & 3;
    const int bm = blockIdx.y * GBM;
    const int bn = blockIdx.x * GBN;

    const int arow = tid >> 1;            // 0..127
    const int ac = (tid & 1) * 8;         // 0 or 8
    const int brow = tid >> 4;            // 0..15
    const int bc = (tid & 15) * 8;        // 0..120

    const float* asrc0 = &A[(size_t)(bm + arow) * Kd + ac];

    float acc[16][4];
#pragma unroll
    for (int i = 0; i < 16; i++)
#pragma unroll
        for (int j = 0; j < 4; j++) acc[i][j] = 0.0f;

    const int nk = Kd / GBK;

    // prologue: tile 0
    {
        cpa16(sb + (arow * ASTR + ac) * 4, asrc0);
        cpa16(sb + (arow * ASTR + ac + 4) * 4, asrc0 + 4);
        cpa16(sbB + (brow * BSTR + bc) * 4, &W[(size_t)brow * N + bn + bc]);
        cpa16(sbB + (brow * BSTR + bc + 4) * 4, &W[(size_t)brow * N + bn + bc + 4]);
        cpa_commit();
    }

    for (int kt = 0; kt < nk; kt++) {
        const int buf = kt & 1;
        const int abuf = buf * GBM * ASTR;
        const int bbuf = buf * GBK * BSTR;
        if (kt + 1 < nk) {
            const int k0 = (kt + 1) * GBK;
            const int nb = (kt + 1) & 1;
            cpa16(sb + (nb * GBM * ASTR + arow * ASTR + ac) * 4, asrc0 + k0);
            cpa16(sb + (nb * GBM * ASTR + arow * ASTR + ac + 4) * 4, asrc0 + k0 + 4);
            cpa16(sbB + (nb * GBK * BSTR + brow * BSTR + bc) * 4,
                  &W[(size_t)(k0 + brow) * N + bn + bc]);
            cpa16(sbB + (nb * GBK * BSTR + brow * BSTR + bc + 4) * 4,
                  &W[(size_t)(k0 + brow) * N + bn + bc + 4]);
        }
        cpa_commit();
        cpa_wait1();
        __syncthreads();

#pragma unroll
        for (int ks = 0; ks < 2; ks++) {
            const int kb = ks * 8;
            unsigned bf[4][2];
#pragma unroll
            for (int nt = 0; nt < 4; nt++) {
                const int n = wn + nt * 8 + r4;
                bf[nt][0] = b2tf(Bs[bbuf + (kb + c4) * BSTR + n]);
                bf[nt][1] = b2tf(Bs[bbuf + (kb + c4 + 4) * BSTR + n]);
            }
#pragma unroll
            for (int mt = 0; mt < 4; mt++) {
                const int m = wm + mt * 16 + r4;
                unsigned a0 = b2tf(As[abuf + m * ASTR + kb + c4]);
                unsigned a1 = b2tf(As[abuf + (m + 8) * ASTR + kb + c4]);
                unsigned a2 = b2tf(As[abuf + m * ASTR + kb + c4 + 4]);
                unsigned a3 = b2tf(As[abuf + (m + 8) * ASTR + kb + c4 + 4]);
#pragma unroll
                for (int nt = 0; nt < 4; nt++)
                    mma_tf32(acc[mt * 4 + nt], a0, a1, a2, a3, bf[nt][0], bf[nt][1]);
            }
        }
        __syncthreads();
    }

    // epilogue
#pragma unroll
    for (int mt = 0; mt < 4; mt++) {
#pragma unroll
        for (int nt = 0; nt < 4; nt++) {
            const int row0 = bm + wm + mt * 16 + r4;
            const int col = bn + wn + nt * 8 + 2 * c4;
            float* c0 = &C[(size_t)row0 * N + col];
            float* c1 = &C[(size_t)(row0 + 8) * N + col];
            const float b0 = bias[col], b1 = bias[col + 1];
            c0[0] = (acc[mt * 4 + nt][0] + b0) * scale;
            c0[1] = (acc[mt * 4 + nt][1] + b1) * scale;
            c1[0] = (acc[mt * 4 + nt][2] + b0) * scale;
            c1[1] = (acc[mt * 4 + nt][3] + b1) * scale;
        }
    }
}

// ---------------- Flash attention (tf32 mma, wide warp tiles) ----------------
// grid (S/128, NHEADS, B), 128 threads = 4 warps, each warp owns 32 q rows
// (2 row-groups of 16). Q fragments in registers (rounded once). K/V double-
// buffered raw-fp32 via cp.async, rounded at fragment load. P staged rounded.
#define FBQ 128
#define QSTR 68   // K buffer stride (==4 mod 32)
#define VSTR 72   // V buffer stride (==8 mod 32)
#define PSTR 68
#define FLASH_SMEM ((2 * 64 * QSTR + 2 * 64 * VSTR + FBQ * PSTR) * 4)

__global__ __launch_bounds__(128) void flash_tf32(
    const float* __restrict__ Q, const float* __restrict__ K,
    const float* __restrict__ V, const float* __restrict__ mask,
    float* __restrict__ Ctx)
{
    extern __shared__ unsigned fsm[];
    unsigned* Ks = fsm;                         // [2][64][QSTR] raw fp32
    unsigned* Vs = fsm + 2 * 64 * QSTR;         // [2][64][VSTR] raw fp32
    unsigned* Ps = Vs + 2 * 64 * VSTR;          // [128][PSTR]   tf32
    const unsigned sb = (unsigned)__cvta_generic_to_shared(fsm);
    const unsigned sbV = sb + 2 * 64 * QSTR * 4;

    const int tid = threadIdx.x;
    const int lane = tid & 31;
    const int w = tid >> 5;
    const int r4 = lane >> 2;
    const int c4 = lane & 3;
    const int qb = blockIdx.x * FBQ;
    const int h = blockIdx.y;
    const int b = blockIdx.z;

    const size_t base = (size_t)b * SS * HH;
    const int hoff = h * DH;
    const float* maskb = mask + (size_t)b * SS * SS;

    const int srow = tid >> 1;            // 0..63
    const int scol0 = (tid & 1) * 32;     // 0 or 32

    // prologue: issue K/V tile 0 copies
    {
        const float* kp = &K[base + (size_t)srow * HH + hoff + scol0];
        const float* vp = &V[base + (size_t)srow * HH + hoff + scol0];
#pragma unroll
        for (int j = 0; j < 8; j++) {
            cpa16(sb + (srow * QSTR + scol0 + j * 4) * 4, kp + j * 4);
            cpa16(sbV + (srow * VSTR + scol0 + j * 4) * 4, vp + j * 4);
        }
        cpa_commit();
    }

    // load Q fragments (scaled by 0.125 in projection), round once
    unsigned qf[8][8];   // [ks][g*4 + j]
#pragma unroll
    for (int ks = 0; ks < 8; ks++) {
#pragma unroll
        for (int g = 0; g < 2; g++) {
            const size_t R0 = (size_t)(qb + 32 * w + 16 * g + r4) * HH + base;
            const int col = hoff + ks * 8 + c4;
            qf[ks][g * 4 + 0] = f2tf(Q[R0 + col]);
            qf[ks][g * 4 + 1] = f2tf(Q[R0 + 8 * HH + col]);
            qf[ks][g * 4 + 2] = f2tf(Q[R0 + col + 4]);
            qf[ks][g * 4 + 3] = f2tf(Q[R0 + 8 * HH + col + 4]);
        }
    }

    float oc[2][8][4];
#pragma unroll
    for (int g = 0; g < 2; g++)
#pragma unroll
        for (int nt = 0; nt < 8; nt++)
#pragma unroll
            for (int j = 0; j < 4; j++) oc[g][nt][j] = 0.0f;
    float mx[2][2], ls[2][2];
#pragma unroll
    for (int g = 0; g < 2; g++) {
        mx[g][0] = -1e30f; mx[g][1] = -1e30f;
        ls[g][0] = 0.0f;   ls[g][1] = 0.0f;
    }

    const int NT = SS / 64;
    for (int t = 0; t < NT; t++) {
        const int k0 = t * 64;
        const int buf = t & 1;
        const int kbuf = buf * 64 * QSTR;
        const int vbuf = buf * 64 * VSTR;

        if (t + 1 < NT) {
            const int nb = (t + 1) & 1;
            const float* kp = &K[base + (size_t)(k0 + 64 + srow) * HH + hoff + scol0];
            const float* vp = &V[base + (size_t)(k0 + 64 + srow) * HH + hoff + scol0];
#pragma unroll
            for (int j = 0; j < 8; j++) {
                cpa16(sb + (nb * 64 * QSTR + srow * QSTR + scol0 + j * 4) * 4, kp + j * 4);
                cpa16(sbV + (nb * 64 * VSTR + srow * VSTR + scol0 + j * 4) * 4, vp + j * 4);
            }
        }
        cpa_commit();
        cpa_wait1();
        __syncthreads();

        // ---- S = Q @ K^T (warp: 32q x 64k) ----
        float sc[2][8][4];
#pragma unroll
        for (int g = 0; g < 2; g++)
#pragma unroll
            for (int nt = 0; nt < 8; nt++)
#pragma unroll
                for (int j = 0; j < 4; j++) sc[g][nt][j] = 0.0f;

#pragma unroll
        for (int ks = 0; ks < 8; ks++) {
            const int kb = ks * 8;
            unsigned bf0[8], bf1[8];
#pragma unroll
            for (int nt = 0; nt < 8; nt++) {
                bf0[nt] = b2tf(Ks[kbuf + (nt * 8 + r4) * QSTR + kb + c4]);
                bf1[nt] = b2tf(Ks[kbuf + (nt * 8 + r4) * QSTR + kb + c4 + 4]);
            }
#pragma unroll
            for (int g = 0; g < 2; g++)
#pragma unroll
                for (int nt = 0; nt < 8; nt++)
                    mma_tf32(sc[g][nt], qf[ks][g * 4 + 0], qf[ks][g * 4 + 1],
                             qf[ks][g * 4 + 2], qf[ks][g * 4 + 3], bf0[nt], bf1[nt]);
        }

        // ---- mask + online softmax per group ----
#pragma unroll
        for (int g = 0; g < 2; g++) {
            const int row0 = qb + 32 * w + 16 * g + r4;
            const size_t mb0 = (size_t)row0 * SS + k0 + 2 * c4;
            const size_t mb1 = mb0 + (size_t)8 * SS;
#pragma unroll
            for (int nt = 0; nt < 8; nt++) {
                const float2 m0v = *(const float2*)&maskb[mb0 + nt * 8];
                const float2 m1v = *(const float2*)&maskb[mb1 + nt * 8];
                sc[g][nt][0] += m0v.x; sc[g][nt][1] += m0v.y;
                sc[g][nt][2] += m1v.x; sc[g][nt][3] += m1v.y;
            }
            float tm0 = -1e30f, tm1 = -1e30f;
#pragma unroll
            for (int nt = 0; nt < 8; nt++) {
                tm0 = fmaxf(tm0, fmaxf(sc[g][nt][0], sc[g][nt][1]));
                tm1 = fmaxf(tm1, fmaxf(sc[g][nt][2], sc[g][nt][3]));
            }
#pragma unroll
            for (int o = 1; o <= 2; o <<= 1) {
                tm0 = fmaxf(tm0, __shfl_xor_sync(0xffffffffu, tm0, o));
                tm1 = fmaxf(tm1, __shfl_xor_sync(0xffffffffu, tm1, o));
            }
            const float nm0 = fmaxf(mx[g][0], tm0), nm1 = fmaxf(mx[g][1], tm1);
            float s0 = 0.0f, s1 = 0.0f;
#pragma unroll
            for (int nt = 0; nt < 8; nt++) {
                sc[g][nt][0] = __expf(sc[g][nt][0] - nm0);
                sc[g][nt][1] = __expf(sc[g][nt][1] - nm0);
                sc[g][nt][2] = __expf(sc[g][nt][2] - nm1);
                sc[g][nt][3] = __expf(sc[g][nt][3] - nm1);
                s0 += sc[g][nt][0] + sc[g][nt][1];
                s1 += sc[g][nt][2] + sc[g][nt][3];
            }
#pragma unroll
            for (int o = 1; o <= 2; o <<= 1) {
                s0 += __shfl_xor_sync(0xffffffffu, s0, o);
                s1 += __shfl_xor_sync(0xffffffffu, s1, o);
            }
            const float e0 = __expf(mx[g][0] - nm0), e1 = __expf(mx[g][1] - nm1);
            ls[g][0] = ls[g][0] * e0 + s0; mx[g][0] = nm0;
            ls[g][1] = ls[g][1] * e1 + s1; mx[g][1] = nm1;
#pragma unroll
            for (int nt = 0; nt < 8; nt++) {
                oc[g][nt][0] *= e0; oc[g][nt][1] *= e0;
                oc[g][nt][2] *= e1; oc[g][nt][3] *= e1;
            }
        }

        // ---- stage P rounded to tf32 (warp-private rows) ----
#pragma unroll
        for (int g = 0; g < 2; g++) {
            const int pr = (32 * w + 16 * g + r4) * PSTR;
#pragma unroll
            for (int nt = 0; nt < 8; nt++) {
                *(uint2*)&Ps[pr + nt * 8 + 2 * c4] =
                    make_uint2(f2tf(sc[g][nt][0]), f2tf(sc[g][nt][1]));
                *(uint2*)&Ps[pr + 8 * PSTR + nt * 8 + 2 * c4] =
                    make_uint2(f2tf(sc[g][nt][2]), f2tf(sc[g][nt][3]));
            }
        }
        __syncwarp();

        // ---- O += P @ V ----
#pragma unroll
        for (int ks = 0; ks < 8; ks++) {
            const int kb = ks * 8;
            unsigned bf0[8], bf1[8];
#pragma unroll
            for (int nt = 0; nt < 8; nt++) {
                bf0[nt] = b2tf(Vs[vbuf + (kb + c4) * VSTR + nt * 8 + r4]);
                bf1[nt] = b2tf(Vs[vbuf + (kb + c4 + 4) * VSTR + nt * 8 + r4]);
            }
#pragma unroll
            for (int g = 0; g < 2; g++) {
                const int pr = (32 * w + 16 * g + r4) * PSTR;
                unsigned a0 = Ps[pr + kb + c4];
                unsigned a1 = Ps[pr + 8 * PSTR + kb + c4];
                unsigned a2 = Ps[pr + kb + c4 + 4];
                unsigned a3 = Ps[pr + 8 * PSTR + kb + c4 + 4];
#pragma unroll
                for (int nt = 0; nt < 8; nt++)
                    mma_tf32(oc[g][nt], a0, a1, a2, a3, bf0[nt], bf1[nt]);
            }
        }
        __syncthreads();
    }

    // epilogue
#pragma unroll
    for (int g = 0; g < 2; g++) {
        const float il0 = 1.0f / ls[g][0], il1 = 1.0f / ls[g][1];
        const size_t R0 = base + (size_t)(qb + 32 * w + 16 * g + r4) * HH;
#pragma unroll
        for (int nt = 0; nt < 8; nt++) {
            const int col = hoff + nt * 8 + 2 * c4;
            *(float2*)&Ctx[R0 + col] =
                make_float2(oc[g][nt][0] * il0, oc[g][nt][1] * il0);
            *(float2*)&Ctx[R0 + 8 * HH + col] =
                make_float2(oc[g][nt][2] * il1, oc[g][nt][3] * il1);
        }
    }
}

// ---------------- launch -----------------------------------------------------
extern "C" void kernel_launch(void* const* d_in, const int* in_sizes, int n_in,
                              void* d_out, int out_size)
{
    const float* key   = (const float*)d_in[0];
    const float* value = (const float*)d_in[1];
    const float* query = (const float*)d_in[2];
    const float* mask  = (const float*)d_in[3];
    const float* Wq    = (const float*)d_in[4];
    const float* bq    = (const float*)d_in[5];
    const float* Wk    = (const float*)d_in[6];
    const float* bk    = (const float*)d_in[7];
    const float* Wv    = (const float*)d_in[8];
    const float* bv    = (const float*)d_in[9];
    const float* Wo    = (const float*)d_in[10];
    const float* bo    = (const float*)d_in[11];
    float* out = (float*)d_out;

    float *gq, *gk, *gv, *gctx;
    cudaGetSymbolAddress((void**)&gq, g_q);
    cudaGetSymbolAddress((void**)&gk, g_k);
    cudaGetSymbolAddress((void**)&gv, g_v);
    cudaGetSymbolAddress((void**)&gctx, g_ctx);
    cudaFuncSetAttribute(gemm_tf32,
                         cudaFuncAttributeMaxDynamicSharedMemorySize, GEMM_SMEM);
    cudaFuncSetAttribute(flash_tf32,
                         cudaFuncAttributeMaxDynamicSharedMemorySize, FLASH_SMEM);

    dim3 ggrid(HH / GBN, MM / GBM);   // (8, 32)

    gemm_tf32<<<ggrid, 256, GEMM_SMEM>>>(query, Wq, bq, gq, MM, HH, HH, 0.125f);
    gemm_tf32<<<ggrid, 256, GEMM_SMEM>>>(key,   Wk, bk, gk, MM, HH, HH, 1.0f);
    gemm_tf32<<<ggrid, 256, GEMM_SMEM>>>(value, Wv, bv, gv, MM, HH, HH, 1.0f);

    dim3 fgrid(SS / FBQ, NHEADS, BB); // (16, 16, 2)
    flash_tf32<<<fgrid, 128, FLASH_SMEM>>>(gq, gk, gv, mask, gctx);

    gemm_tf32<<<ggrid, 256, GEMM_SMEM>>>(gctx, Wo, bo, out, MM, HH, HH, 1.0f);
}